// round 14
// baseline (speedup 1.0000x reference)
#include <cuda_runtime.h>
#include <cuda_fp16.h>
#include <cstdint>
#include <math.h>

// ---------------- problem constants ----------------
#define B_        16
#define C_        512
#define H_        16
#define W_        300
#define HO_       10
#define KG_       10
#define KC_       8
#define OUT_      5994
#define KDIM      3584        // C_ * 7
#define NDIM      48000       // B_ * HO_ * W_
#define MPAD      640
#define MREAL     522
#define HWX       4800        // H_*W_
#define BSTR      2457600     // C_*H_*W_
#define P_        3000        // HO_*W_
#define FEAT_BSTR 1536000     // C_*P_
#define SCOR_BSTR 30000       // KG_*P_
#define XT_ROWS   (B_*H_*W_)  // 76800

// main GEMM tiling: CTA 128ch x 256pos, 8 warps (2m x 4n), warp tile 64x64
#define MT        128
#define NT        256
#define NCHUNK    112         // KDIM / 32
#define STAGES    4
#define ROWB      80          // padded smem row stride (32 fp16 = 64B + 16B pad)
#define TILE_A_B  10240       // 128 rows * 80B
#define BUF_B     30720       // A | X
#define SMEM_TOTAL (STAGES*BUF_B)  // 122880

// score GEMM: k-split
#define KSPLIT    4
#define SCHUNK    (NCHUNK / KSPLIT)   // 28
#define SNT       128
#define S_ATILE   1280        // 16 rows * 80B
#define S_BUF     11520       // A 1280 | B 10240
#define S_SMEM    (2*S_BUF)   // 23040

// agg p-split
#define PSPLIT    4
#define PSEG      (P_ / PSPLIT)       // 750

// ---------------- device scratch ----------------
__device__ __half g_wh[MPAD * KDIM];
__device__ float g_bias[MPAD];
__device__ __half g_xh[XT_ROWS * C_];
__device__ __half g_feats[B_ * C_ * HO_ * W_];
__device__ float g_scores[B_ * KG_ * HO_ * W_];
__device__ float g_assign[B_ * KG_ * HO_ * W_];
__device__ float g_asum[B_ * KC_];
__device__ float g_agg[B_ * KC_ * C_];
__device__ float g_vlad[B_ * KC_ * C_];

// ---------------- helpers ----------------
__device__ __forceinline__ uint32_t smem_u32(const void* p) {
    uint32_t a;
    asm("{ .reg .u64 t; cvta.to.shared.u64 t, %1; cvt.u32.u64 %0, t; }" : "=r"(a) : "l"(p));
    return a;
}
__device__ __forceinline__ void ldsm4(uint32_t* r, uint32_t addr) {
    asm volatile("ldmatrix.sync.aligned.m8n8.x4.shared.b16 {%0,%1,%2,%3}, [%4];"
                 : "=r"(r[0]), "=r"(r[1]), "=r"(r[2]), "=r"(r[3]) : "r"(addr));
}
__device__ __forceinline__ void mma_f16(float* c, const uint32_t* a, const uint32_t* b) {
    asm volatile(
        "mma.sync.aligned.m16n8k16.row.col.f32.f16.f16.f32 "
        "{%0,%1,%2,%3},{%4,%5,%6,%7},{%8,%9},{%0,%1,%2,%3};"
        : "+f"(c[0]), "+f"(c[1]), "+f"(c[2]), "+f"(c[3])
        : "r"(a[0]), "r"(a[1]), "r"(a[2]), "r"(a[3]), "r"(b[0]), "r"(b[1]));
}
#define CP_ASYNC16(s, g) \
    asm volatile("cp.async.cg.shared.global [%0], [%1], 16;" :: "r"(s), "l"(g))
#define CP_COMMIT()  asm volatile("cp.async.commit_group;" ::: "memory")
#define CP_WAIT2()   asm volatile("cp.async.wait_group 2;" ::: "memory")

// ---------------- K0: pack weights (kh-major K) fp16 + bias ----------------
__global__ void pack_kernel(const float* __restrict__ conv_w,
                            const float* __restrict__ conv_b,
                            const float* __restrict__ cc_w,
                            const float* __restrict__ cc_b) {
    int i = blockIdx.x * blockDim.x + threadIdx.x;
    if (i < MPAD * KDIM) {
        int m = i / KDIM, kk = i - m * KDIM;     // kk = kh*512 + ci
        int kh = kk >> 9, ci = kk & 511;
        float v = 0.f;
        if (m < 512)      v = conv_w[m * KDIM + ci * 7 + kh];
        else if (m < 522) v = cc_w[(m - 512) * KDIM + ci * 7 + kh];
        g_wh[i] = __float2half_rn(v);
    }
    if (i < MPAD) {
        float bv = 0.f;
        if (i < 512)      bv = conv_b[i];
        else if (i < 522) bv = cc_b[i - 512];
        g_bias[i] = bv;
    }
}

// ---------------- K0c: init scores with bias + zero agg ----------------
__global__ void init_scores(const float* __restrict__ cc_b) {
    int i = blockIdx.x * 256 + threadIdx.x;
    if (i < B_ * SCOR_BSTR) {
        int k = (i % SCOR_BSTR) / P_;
        g_scores[i] = cc_b[k];
    }
    if (i < B_ * KC_ * C_) g_agg[i] = 0.f;
}

// ---------------- K0b: transpose x -> [b,h,w,c] fp16 ----------------
__global__ void xt_kernel(const float* __restrict__ x) {
    __shared__ float xs[32][33];
    const int ct = blockIdx.x & 15;        // channel tile (16)
    const int wt = blockIdx.x >> 4;        // w tile (10)
    const int b  = blockIdx.y >> 4;
    const int h  = blockIdx.y & 15;
    const int tid = threadIdx.x;
    const float* xb = x + (size_t)b * BSTR + h * W_;
#pragma unroll
    for (int it = 0; it < 4; it++) {
        int e = tid + 256 * it;
        int c = e >> 5, w = e & 31;
        int gw = wt * 32 + w;
        xs[c][w] = (gw < W_) ? xb[(size_t)(ct * 32 + c) * HWX + gw] : 0.f;
    }
    __syncthreads();
    const size_t rowb = ((size_t)(b * 16 + h)) * W_;
#pragma unroll
    for (int it = 0; it < 4; it++) {
        int e = tid + 256 * it;
        int w = e >> 5, c = e & 31;
        int gw = wt * 32 + w;
        if (gw < W_)
            g_xh[(rowb + gw) * C_ + ct * 32 + c] = __float2half_rn(xs[c][w]);
    }
}

// ---------------- K1: feats GEMM, 128x256 tile, 4-stage cp.async ----------------
__global__ void __launch_bounds__(256, 1) conv_mma() {
    extern __shared__ char sm[];
    const uint32_t smb = smem_u32(sm);
    const int tid  = threadIdx.x;
    const int wid  = tid >> 5;
    const int lane = tid & 31;
    const int mBase = blockIdx.y * MT;
    const int nBase = blockIdx.x * NT;

    // ---- loader setup ----
    const int arow = tid & 127;
    const int thi  = tid >> 7;
    int n = nBase + tid;
    if (n >= NDIM) n = NDIM - 1;     // clamp (tail CTA); stores are guarded
    const int b2  = n / P_;
    const int rem = n - b2 * P_;
    const int ho  = rem / W_;
    const int w   = rem - ho * W_;
    const size_t bRowBase = ((size_t)(b2 * 16 + ho) * W_ + w) * C_;

    const __half* aPtr[2];
    uint32_t aSoff[2];
#pragma unroll
    for (int it = 0; it < 2; it++) {
        const int c16 = thi * 2 + it;
        aPtr[it]  = g_wh + (size_t)(mBase + arow) * KDIM + c16 * 8;
        aSoff[it] = (uint32_t)(arow * ROWB + c16 * 16);
    }
    const __half* xPtr = g_xh + bRowBase;
    const uint32_t xSoff = (uint32_t)(TILE_A_B + tid * ROWB);

    // ---- per-warp ldmatrix base addresses (2m x 4n warps, 64x64 tiles) ----
    const int mw = wid >> 2;           // 0..1
    const int nw = wid & 3;            // 0..3
    const uint32_t aAddr = (uint32_t)((mw * 64 + (lane & 15)) * ROWB + ((lane >> 4) << 4));
    const uint32_t bAddr = (uint32_t)(TILE_A_B +
                           (nw * 64 + (lane & 7) + ((lane >> 4) << 3)) * ROWB +
                           (((lane >> 3) & 1) << 4));

    float acc[4][8][4];
#pragma unroll
    for (int i = 0; i < 4; i++)
#pragma unroll
        for (int j = 0; j < 8; j++)
#pragma unroll
            for (int r = 0; r < 4; r++) acc[i][j][r] = 0.f;

    auto issue_chunk = [&](int chunk, uint32_t sbase) {
        const int k0  = chunk << 5;
        const int kh  = k0 >> 9;
        const int ci0 = k0 & 511;
        const size_t bo = (size_t)kh * (W_ * C_) + ci0;
#pragma unroll
        for (int c = 0; c < 2; c++)
            CP_ASYNC16(sbase + aSoff[c], aPtr[c] + k0);
#pragma unroll
        for (int c = 0; c < 4; c++)
            CP_ASYNC16(sbase + xSoff + c * 16, xPtr + bo + c * 8);
    };

    // prologue: stages 0..2 in flight
#pragma unroll
    for (int s = 0; s < STAGES - 1; s++) {
        issue_chunk(s, smb + (uint32_t)s * BUF_B);
        CP_COMMIT();
    }

#pragma unroll 1
    for (int i = 0; i < NCHUNK; i++) {
        CP_WAIT2();              // chunk i resident (2 newer groups outstanding)
        __syncthreads();
        const uint32_t base = smb + (uint32_t)(i & 3) * BUF_B;
#pragma unroll
        for (int q = 0; q < 2; q++) {
            const uint32_t qo = q * 32;
            uint32_t ah[4][4], bf[8][2];
#pragma unroll
            for (int f = 0; f < 4; f++)
                ldsm4(ah[f], base + aAddr + f * 1280 + qo);
#pragma unroll
            for (int t = 0; t < 4; t++) {
                uint32_t r[4];
                ldsm4(r, base + bAddr + t * 1280 + qo);
                bf[2 * t][0] = r[0]; bf[2 * t][1] = r[1];
                bf[2 * t + 1][0] = r[2]; bf[2 * t + 1][1] = r[3];
            }
#pragma unroll
            for (int f = 0; f < 4; f++)
#pragma unroll
                for (int j = 0; j < 8; j++)
                    mma_f16(acc[f][j], ah[f], bf[j]);
        }
        if (i + STAGES - 1 < NCHUNK)
            issue_chunk(i + STAGES - 1, smb + (uint32_t)((i + STAGES - 1) & 3) * BUF_B);
        CP_COMMIT();             // always commit: keeps group count uniform
    }

    // ---- epilogue: bias + relu, fp16 stores (all m < 512), guarded tail ----
    float bias_v[4][2];
#pragma unroll
    for (int f = 0; f < 4; f++)
#pragma unroll
        for (int h = 0; h < 2; h++)
            bias_v[f][h] = g_bias[mBase + mw * 64 + f * 16 + (lane >> 2) + 8 * h];
#pragma unroll
    for (int j = 0; j < 8; j++) {
        const int nj  = nBase + nw * 64 + j * 8 + (lane & 3) * 2;
        if (nj >= NDIM) continue;
        const int bj  = nj / P_;
        const int rj  = nj - bj * P_;
        const size_t fb = (size_t)bj * FEAT_BSTR + rj;
#pragma unroll
        for (int f = 0; f < 4; f++)
#pragma unroll
            for (int h = 0; h < 2; h++) {
                const int m = mBase + mw * 64 + f * 16 + (lane >> 2) + 8 * h;
                __half2 o = __floats2half2_rn(
                    fmaxf(acc[f][j][2 * h]     + bias_v[f][h], 0.f),
                    fmaxf(acc[f][j][2 * h + 1] + bias_v[f][h], 0.f));
                *(__half2*)(g_feats + fb + (size_t)m * P_) = o;
            }
    }
}

// ---------------- K1b: scores GEMM, k-split x4 with atomic merge ----------------
__global__ void __launch_bounds__(128) score_mma() {
    extern __shared__ char sm[];
    const uint32_t smb = smem_u32(sm);
    const int tid  = threadIdx.x;
    const int wid  = tid >> 5;      // 0..3 = n-warp
    const int lane = tid & 31;
    const int nBase = blockIdx.x * SNT;
    const int cBase = blockIdx.y * SCHUNK;     // chunk segment

    // B loader: row = tid, 4 chunks
    const int n   = nBase + tid;
    const int b2  = n / P_;
    const int rem = n - b2 * P_;
    const int ho  = rem / W_;
    const int w   = rem - ho * W_;
    const size_t bRowBase = ((size_t)(b2 * 16 + ho) * W_ + w) * C_;
    // A loader: 64 transfers: 16 rows * 4 chunks (tid < 64)
    const int arow = (tid & 63) >> 2;
    const int ac16 = tid & 3;
    const bool aact = tid < 64;
    const __half* aPtr = g_wh + (size_t)(512 + arow) * KDIM + ac16 * 8;
    const uint32_t aSoff = (uint32_t)(arow * ROWB + ac16 * 16);

    const uint32_t aAddr = (uint32_t)((lane & 15) * ROWB + ((lane >> 4) << 4));
    const uint32_t bAddr = (uint32_t)(S_ATILE +
                           (wid * 32 + (lane & 7) + ((lane >> 4) << 3)) * ROWB +
                           (((lane >> 3) & 1) << 4));

    float acc[4][4];
#pragma unroll
    for (int j = 0; j < 4; j++)
#pragma unroll
        for (int r = 0; r < 4; r++) acc[j][r] = 0.f;

    // prologue: chunk cBase
    {
        const int k0  = cBase << 5;
        const int kh  = k0 >> 9;
        const int ci0 = k0 & 511;
        const size_t bo = (size_t)kh * (W_ * C_) + ci0;
        uint4 vb[4];
#pragma unroll
        for (int c = 0; c < 4; c++) vb[c] = *(const uint4*)(g_xh + bRowBase + bo + c * 8);
        if (aact) *(uint4*)(sm + aSoff) = *(const uint4*)(aPtr + k0);
#pragma unroll
        for (int c = 0; c < 4; c++)
            *(uint4*)(sm + S_ATILE + tid * ROWB + c * 16) = vb[c];
    }
    __syncthreads();

#pragma unroll 1
    for (int i = 0; i < SCHUNK; i++) {
        const int cur = i & 1;
        uint4 va, vb[4];
        const bool hasNext = (i + 1) < SCHUNK;
        if (hasNext) {
            const int k0  = (cBase + i + 1) << 5;
            const int kh  = k0 >> 9;
            const int ci0 = k0 & 511;
            const size_t bo = (size_t)kh * (W_ * C_) + ci0;
            if (aact) va = *(const uint4*)(aPtr + k0);
#pragma unroll
            for (int c = 0; c < 4; c++) vb[c] = *(const uint4*)(g_xh + bRowBase + bo + c * 8);
        }
        {
            const uint32_t base = smb + (uint32_t)cur * S_BUF;
#pragma unroll
            for (int q = 0; q < 2; q++) {
                const uint32_t qo = q * 32;
                uint32_t ah[4], bf[4][2];
                ldsm4(ah, base + aAddr + qo);
#pragma unroll
                for (int t = 0; t < 2; t++) {
                    uint32_t r[4];
                    ldsm4(r, base + bAddr + t * 1280 + qo);
                    bf[2 * t][0] = r[0]; bf[2 * t][1] = r[1];
                    bf[2 * t + 1][0] = r[2]; bf[2 * t + 1][1] = r[3];
                }
#pragma unroll
                for (int j = 0; j < 4; j++)
                    mma_f16(acc[j], ah, bf[j]);
            }
        }
        if (hasNext) {
            char* bb = sm + (cur ^ 1) * S_BUF;
            if (aact) *(uint4*)(bb + aSoff) = va;
#pragma unroll
            for (int c = 0; c < 4; c++)
                *(uint4*)(bb + S_ATILE + tid * ROWB + c * 16) = vb[c];
        }
        __syncthreads();
    }

    // epilogue: rows 0..9 real -> atomic merge into scores
#pragma unroll
    for (int j = 0; j < 4; j++) {
        const int nj  = nBase + wid * 32 + j * 8 + (lane & 3) * 2;
        const int bj  = nj / P_;
        const int rj  = nj - bj * P_;
        const size_t sb = (size_t)bj * SCOR_BSTR + rj;
#pragma unroll
        for (int h = 0; h < 2; h++) {
            const int m = (lane >> 2) + 8 * h;
            if (m < KG_) {
                atomicAdd(g_scores + sb + (size_t)m * P_,     acc[j][2 * h]);
                atomicAdd(g_scores + sb + (size_t)m * P_ + 1, acc[j][2 * h + 1]);
            }
        }
    }
}

// ---------------- K2: softmax over 10 cluster channels ----------------
__global__ void softmax_kernel() {
    int q = blockIdx.x * 256 + threadIdx.x;
    if (q >= NDIM) return;
    int b = q / P_;
    int rem = q - b * P_;
    int base = b * SCOR_BSTR + rem;
    float s[KG_];
    float mx = -1e30f;
#pragma unroll
    for (int k = 0; k < KG_; k++) { s[k] = g_scores[base + k * P_]; mx = fmaxf(mx, s[k]); }
    float sum = 0.f;
#pragma unroll
    for (int k = 0; k < KG_; k++) { s[k] = expf(s[k] - mx); sum += s[k]; }
    float inv = 1.f / sum;
#pragma unroll
    for (int k = 0; k < KG_; k++) g_assign[base + k * P_] = s[k] * inv;
}

// ---------------- K2b: asum ----------------
__global__ void asum_kernel() {
    int b = blockIdx.x >> 3, k = blockIdx.x & 7;
    const float* a = g_assign + b * SCOR_BSTR + k * P_;
    float s = 0.f;
    for (int i = threadIdx.x; i < P_; i += 256) s += a[i];
    __shared__ float red[256];
    red[threadIdx.x] = s;
    __syncthreads();
    for (int st = 128; st > 0; st >>= 1) {
        if (threadIdx.x < st) red[threadIdx.x] += red[threadIdx.x + st];
        __syncthreads();
    }
    if (threadIdx.x == 0) g_asum[blockIdx.x] = red[0];
}

// ---------------- K3: agg, p-split x4, atomic merge ----------------
__global__ void agg_kernel() {
    __shared__ float fs[64][65];
    __shared__ float as[8][64];
    const int b  = blockIdx.y;
    const int c0 = blockIdx.x * 64;
    const int pg = blockIdx.z;           // p segment
    const int t = threadIdx.x;
    const int k = t >> 6;
    const int c = t & 63;
    const __half* fb = g_feats + (size_t)b * FEAT_BSTR + (size_t)c0 * P_;
    const float* ab = g_assign + b * SCOR_BSTR;
    float acc0 = 0.f, acc1 = 0.f;
    const int pStart = pg * PSEG;
    const int pEnd   = pStart + PSEG;
    for (int p0 = pStart; p0 < pEnd; p0 += 64) {
        int pc = pEnd - p0; if (pc > 64) pc = 64;
#pragma unroll
        for (int idx = t; idx < 4096; idx += 256) {
            int cc = idx >> 6, pp = idx & 63;
            fs[cc][pp] = (pp < pc) ? __half2float(fb[cc * P_ + p0 + pp]) : 0.f;
        }
#pragma unroll
        for (int idx = t; idx < 512; idx += 256) {
            int kk = idx >> 6, pp = idx & 63;
            as[kk][pp] = (pp < pc) ? ab[kk * P_ + p0 + pp] : 0.f;
        }
        __syncthreads();
#pragma unroll
        for (int p = 0; p < 64; p++) {
            float f = fs[c][p];
            acc0 = fmaf(as[k][p], f, acc0);
            acc1 = fmaf(as[k + 4][p], f, acc1);
        }
        __syncthreads();
    }
    atomicAdd(g_agg + b * 4096 + k * 512 + c0 + c,       acc0);
    atomicAdd(g_agg + b * 4096 + (k + 4) * 512 + c0 + c, acc1);
}

// ---------------- K4: residual + L2 normalize ----------------
__global__ void vlad_kernel(const float* __restrict__ centroids) {
    const int b = blockIdx.x >> 3, k = blockIdx.x & 7;
    const int t = threadIdx.x;
    const float asum = g_asum[blockIdx.x];
    const float* aggp = g_agg + b * 4096 + k * 512;
    const float* cen = centroids + k * 512;
    float r0 = aggp[t] - asum * cen[t];
    float r1 = aggp[t + 256] - asum * cen[t + 256];
    __shared__ float red[256];
    red[t] = r0 * r0 + r1 * r1;
    __syncthreads();
    for (int st = 128; st > 0; st >>= 1) {
        if (t < st) red[t] += red[t + st];
        __syncthreads();
    }
    __shared__ float scale_s;
    if (t == 0) scale_s = 1.f / fmaxf(sqrtf(red[0]), 1e-12f);
    __syncthreads();
    float sc = scale_s;
    g_vlad[b * 4096 + k * 512 + t] = r0 * sc;
    g_vlad[b * 4096 + k * 512 + t + 256] = r1 * sc;
}

// ---------------- K5: emb, one CTA per channel, fc_w row staged in smem ------
__global__ void __launch_bounds__(128) emb_kernel(const float* __restrict__ fc_w,
                                                  const float* __restrict__ fc_b,
                                                  float* __restrict__ out) {
    const int co = blockIdx.x;
    __shared__ __align__(16) float ws[4096];
    const int t = threadIdx.x;          // 128
    const int wid = t >> 5, lane = t & 31;
    {
        const float4* wr = (const float4*)(fc_w + (size_t)co * 4096);
        float4* wsv = (float4*)ws;
#pragma unroll
        for (int i = t; i < 1024; i += 128) wsv[i] = wr[i];
    }
    __syncthreads();
    const float bv = fc_b[co];
    const float4* wsv = (const float4*)ws;
#pragma unroll
    for (int bb = 0; bb < 4; bb++) {
        const int b = wid * 4 + bb;
        const float4* v = (const float4*)(g_vlad + b * 4096);
        float s = 0.f;
        for (int i = lane; i < 1024; i += 32) {
            float4 a = v[i], w4 = wsv[i];
            s += a.x * w4.x + a.y * w4.y + a.z * w4.z + a.w * w4.w;
        }
#pragma unroll
        for (int off = 16; off > 0; off >>= 1)
            s += __shfl_down_sync(0xffffffff, s, off);
        if (lane == 0) out[b * 512 + co] = fmaxf(s + bv, 0.f);
    }
}

// ---------------- K6: logit, one CTA per output row, w staged in smem ----------
__global__ void __launch_bounds__(128) logit_kernel(const float* __restrict__ emb,
                                                    const float* __restrict__ lw,
                                                    float* __restrict__ out) {
    const int o = blockIdx.x;
    __shared__ __align__(16) float ws[512];
    const int t = threadIdx.x;          // 128
    const int wid = t >> 5, lane = t & 31;
    {
        const float4* wr = (const float4*)(lw + (size_t)o * 512);
        float4* wsv = (float4*)ws;
#pragma unroll
        for (int i = t; i < 128; i += 128) wsv[i] = wr[i];
    }
    __syncthreads();
    const float4* wsv = (const float4*)ws;
#pragma unroll
    for (int bb = 0; bb < 4; bb++) {
        const int b = wid * 4 + bb;
        const float4* e = (const float4*)(emb + b * 512);
        float s = 0.f;
#pragma unroll
        for (int i = lane; i < 128; i += 32) {
            float4 a = e[i], w4 = wsv[i];
            s += a.x * w4.x + a.y * w4.y + a.z * w4.z + a.w * w4.w;
        }
#pragma unroll
        for (int off = 16; off > 0; off >>= 1)
            s += __shfl_down_sync(0xffffffff, s, off);
        if (lane == 0) out[b * OUT_ + o] = s;
    }
}

// ---------------- launch ----------------
extern "C" void kernel_launch(void* const* d_in, const int* in_sizes, int n_in,
                              void* d_out, int out_size) {
    const float* x5        = (const float*)d_in[0];
    const float* conv_w    = (const float*)d_in[5];
    const float* conv_b    = (const float*)d_in[6];
    const float* cc_w      = (const float*)d_in[7];
    const float* cc_b      = (const float*)d_in[8];
    const float* centroids = (const float*)d_in[9];
    const float* fc_w      = (const float*)d_in[10];
    const float* fc_b      = (const float*)d_in[11];
    const float* logit_w   = (const float*)d_in[12];
    float* out = (float*)d_out;

    // lazy one-time setup (first call happens OUTSIDE graph capture)
    static cudaStream_t s2 = nullptr;
    static cudaEvent_t evA = nullptr, evB = nullptr, evJoin = nullptr;
    if (s2 == nullptr) {
        int loPri, hiPri;
        cudaDeviceGetStreamPriorityRange(&loPri, &hiPri);
        cudaStreamCreateWithPriority(&s2, cudaStreamNonBlocking, loPri);
        cudaEventCreateWithFlags(&evA, cudaEventDisableTiming);
        cudaEventCreateWithFlags(&evB, cudaEventDisableTiming);
        cudaEventCreateWithFlags(&evJoin, cudaEventDisableTiming);
        cudaFuncSetAttribute(conv_mma, cudaFuncAttributeMaxDynamicSharedMemorySize, SMEM_TOTAL);
    }

    // prologue fork: s2 = pack + init, main = xt
    cudaEventRecord(evA, 0);
    cudaStreamWaitEvent(s2, evA, 0);
    pack_kernel<<<(MPAD * KDIM + 255) / 256, 256, 0, s2>>>(conv_w, conv_b, cc_w, cc_b);
    init_scores<<<(B_ * SCOR_BSTR + 255) / 256, 256, 0, s2>>>(cc_b);

    xt_kernel<<<dim3(160, 256), 256>>>(x5);

    // cross-join: main needs pack (conv uses g_wh/g_bias); s2 needs xt (score uses g_xh)
    cudaEventRecord(evB, s2);       // pack+init done
    cudaStreamWaitEvent(0, evB, 0); // main waits for weights
    cudaEventRecord(evA, 0);        // xt done (and weights ready on main)
    cudaStreamWaitEvent(s2, evA, 0);

    // fork: score chain on low-priority s2, conv on main
    score_mma<<<dim3(NDIM / SNT, KSPLIT), 128, S_SMEM, s2>>>();
    softmax_kernel<<<(NDIM + 255) / 256, 256, 0, s2>>>();
    asum_kernel<<<B_ * KC_, 256, 0, s2>>>();
    cudaEventRecord(evJoin, s2);

    conv_mma<<<dim3((NDIM + NT - 1) / NT, 4), 256, SMEM_TOTAL>>>();

    // join: agg needs feats (main) + assign (s2)
    cudaStreamWaitEvent(0, evJoin, 0);
    agg_kernel<<<dim3(8, B_, PSPLIT), 256>>>();
    vlad_kernel<<<B_ * KC_, 256>>>(centroids);
    emb_kernel<<<C_, 128>>>(fc_w, fc_b, out);
    logit_kernel<<<OUT_, 128>>>(out, logit_w, out + B_ * C_);
}

// round 15
// speedup vs baseline: 1.0273x; 1.0273x over previous
#include <cuda_runtime.h>
#include <cuda_fp16.h>
#include <cstdint>
#include <math.h>

// ---------------- problem constants ----------------
#define B_        16
#define C_        512
#define H_        16
#define W_        300
#define HO_       10
#define KG_       10
#define KC_       8
#define OUT_      5994
#define KDIM      3584        // C_ * 7
#define NDIM      48000       // B_ * HO_ * W_
#define MPAD      640
#define MREAL     522
#define HWX       4800        // H_*W_
#define BSTR      2457600     // C_*H_*W_
#define P_        3000        // HO_*W_
#define FEAT_BSTR 1536000     // C_*P_
#define SCOR_BSTR 30000       // KG_*P_
#define XT_ROWS   (B_*H_*W_)  // 76800

// main GEMM tiling: CTA 128ch x 256pos, 8 warps (2m x 4n), warp tile 64x64
#define MT        128
#define NT        256
#define NCHUNK    112         // KDIM / 32
#define STAGES    4
#define ROWB      80          // padded smem row stride (32 fp16 = 64B + 16B pad)
#define TILE_A_B  10240       // 128 rows * 80B
#define BUF_B     30720       // A | X
#define SMEM_TOTAL (STAGES*BUF_B)  // 122880

// score GEMM: k-split
#define KSPLIT    4
#define SCHUNK    (NCHUNK / KSPLIT)   // 28
#define SNT       128
#define S_ATILE   1280        // 16 rows * 80B
#define S_BUF     11520       // A 1280 | B 10240
#define S_SMEM    (2*S_BUF)   // 23040

// agg p-split
#define PSPLIT    4
#define PSEG      (P_ / PSPLIT)       // 750

// ---------------- device scratch ----------------
__device__ __half g_wh[MPAD * KDIM];
__device__ float g_bias[MPAD];
__device__ __half g_xh[XT_ROWS * C_];
__device__ __half g_feats[B_ * C_ * HO_ * W_];
__device__ float g_scores[B_ * KG_ * HO_ * W_];
__device__ float g_assign[B_ * KG_ * HO_ * W_];
__device__ float g_asum[B_ * KC_];
__device__ float g_agg[B_ * KC_ * C_];
__device__ float g_vlad[B_ * KC_ * C_];

// ---------------- helpers ----------------
__device__ __forceinline__ uint32_t smem_u32(const void* p) {
    uint32_t a;
    asm("{ .reg .u64 t; cvta.to.shared.u64 t, %1; cvt.u32.u64 %0, t; }" : "=r"(a) : "l"(p));
    return a;
}
__device__ __forceinline__ void ldsm4(uint32_t* r, uint32_t addr) {
    asm volatile("ldmatrix.sync.aligned.m8n8.x4.shared.b16 {%0,%1,%2,%3}, [%4];"
                 : "=r"(r[0]), "=r"(r[1]), "=r"(r[2]), "=r"(r[3]) : "r"(addr));
}
__device__ __forceinline__ void mma_f16(float* c, const uint32_t* a, const uint32_t* b) {
    asm volatile(
        "mma.sync.aligned.m16n8k16.row.col.f32.f16.f16.f32 "
        "{%0,%1,%2,%3},{%4,%5,%6,%7},{%8,%9},{%0,%1,%2,%3};"
        : "+f"(c[0]), "+f"(c[1]), "+f"(c[2]), "+f"(c[3])
        : "r"(a[0]), "r"(a[1]), "r"(a[2]), "r"(a[3]), "r"(b[0]), "r"(b[1]));
}
#define CP_ASYNC16(s, g) \
    asm volatile("cp.async.cg.shared.global [%0], [%1], 16;" :: "r"(s), "l"(g))
#define CP_COMMIT()  asm volatile("cp.async.commit_group;" ::: "memory")
#define CP_WAIT2()   asm volatile("cp.async.wait_group 2;" ::: "memory")

// ---------------- K0: pack weights (kh-major K) fp16 + bias ----------------
__global__ void pack_kernel(const float* __restrict__ conv_w,
                            const float* __restrict__ conv_b,
                            const float* __restrict__ cc_w,
                            const float* __restrict__ cc_b) {
    int i = blockIdx.x * blockDim.x + threadIdx.x;
    if (i < MPAD * KDIM) {
        int m = i / KDIM, kk = i - m * KDIM;     // kk = kh*512 + ci
        int kh = kk >> 9, ci = kk & 511;
        float v = 0.f;
        if (m < 512)      v = conv_w[m * KDIM + ci * 7 + kh];
        else if (m < 522) v = cc_w[(m - 512) * KDIM + ci * 7 + kh];
        g_wh[i] = __float2half_rn(v);
    }
    if (i < MPAD) {
        float bv = 0.f;
        if (i < 512)      bv = conv_b[i];
        else if (i < 522) bv = cc_b[i - 512];
        g_bias[i] = bv;
    }
}

// ---------------- K0c: init scores with bias + zero agg ----------------
__global__ void init_scores() {
    int i = blockIdx.x * 256 + threadIdx.x;
    if (i < B_ * SCOR_BSTR) {
        int k = (i % SCOR_BSTR) / P_;
        g_scores[i] = g_bias[512 + k];
    }
    if (i < B_ * KC_ * C_) g_agg[i] = 0.f;
}

// ---------------- K0b: transpose x -> [b,h,w,c] fp16 ----------------
__global__ void xt_kernel(const float* __restrict__ x) {
    __shared__ float xs[32][33];
    const int ct = blockIdx.x & 15;        // channel tile (16)
    const int wt = blockIdx.x >> 4;        // w tile (10)
    const int b  = blockIdx.y >> 4;
    const int h  = blockIdx.y & 15;
    const int tid = threadIdx.x;
    const float* xb = x + (size_t)b * BSTR + h * W_;
#pragma unroll
    for (int it = 0; it < 4; it++) {
        int e = tid + 256 * it;
        int c = e >> 5, w = e & 31;
        int gw = wt * 32 + w;
        xs[c][w] = (gw < W_) ? xb[(size_t)(ct * 32 + c) * HWX + gw] : 0.f;
    }
    __syncthreads();
    const size_t rowb = ((size_t)(b * 16 + h)) * W_;
#pragma unroll
    for (int it = 0; it < 4; it++) {
        int e = tid + 256 * it;
        int w = e >> 5, c = e & 31;
        int gw = wt * 32 + w;
        if (gw < W_)
            g_xh[(rowb + gw) * C_ + ct * 32 + c] = __float2half_rn(xs[c][w]);
    }
}

// ---------------- K1: feats GEMM, 128x256 tile, 4-stage cp.async ----------------
__global__ void __launch_bounds__(256, 1) conv_mma() {
    extern __shared__ char sm[];
    const uint32_t smb = smem_u32(sm);
    const int tid  = threadIdx.x;
    const int wid  = tid >> 5;
    const int lane = tid & 31;
    const int mBase = blockIdx.y * MT;
    const int nBase = blockIdx.x * NT;

    // ---- loader setup ----
    const int arow = tid & 127;
    const int thi  = tid >> 7;
    int n = nBase + tid;
    if (n >= NDIM) n = NDIM - 1;     // clamp (tail CTA); stores are guarded
    const int b2  = n / P_;
    const int rem = n - b2 * P_;
    const int ho  = rem / W_;
    const int w   = rem - ho * W_;
    const size_t bRowBase = ((size_t)(b2 * 16 + ho) * W_ + w) * C_;

    const __half* aPtr[2];
    uint32_t aSoff[2];
#pragma unroll
    for (int it = 0; it < 2; it++) {
        const int c16 = thi * 2 + it;
        aPtr[it]  = g_wh + (size_t)(mBase + arow) * KDIM + c16 * 8;
        aSoff[it] = (uint32_t)(arow * ROWB + c16 * 16);
    }
    const __half* xPtr = g_xh + bRowBase;
    const uint32_t xSoff = (uint32_t)(TILE_A_B + tid * ROWB);

    // ---- per-warp ldmatrix base addresses (2m x 4n warps, 64x64 tiles) ----
    const int mw = wid >> 2;           // 0..1
    const int nw = wid & 3;            // 0..3
    const uint32_t aAddr = (uint32_t)((mw * 64 + (lane & 15)) * ROWB + ((lane >> 4) << 4));
    const uint32_t bAddr = (uint32_t)(TILE_A_B +
                           (nw * 64 + (lane & 7) + ((lane >> 4) << 3)) * ROWB +
                           (((lane >> 3) & 1) << 4));

    float acc[4][8][4];
#pragma unroll
    for (int i = 0; i < 4; i++)
#pragma unroll
        for (int j = 0; j < 8; j++)
#pragma unroll
            for (int r = 0; r < 4; r++) acc[i][j][r] = 0.f;

    auto issue_chunk = [&](int chunk, uint32_t sbase) {
        const int k0  = chunk << 5;
        const int kh  = k0 >> 9;
        const int ci0 = k0 & 511;
        const size_t bo = (size_t)kh * (W_ * C_) + ci0;
#pragma unroll
        for (int c = 0; c < 2; c++)
            CP_ASYNC16(sbase + aSoff[c], aPtr[c] + k0);
#pragma unroll
        for (int c = 0; c < 4; c++)
            CP_ASYNC16(sbase + xSoff + c * 16, xPtr + bo + c * 8);
    };

    // prologue: stages 0..2 in flight
#pragma unroll
    for (int s = 0; s < STAGES - 1; s++) {
        issue_chunk(s, smb + (uint32_t)s * BUF_B);
        CP_COMMIT();
    }

#pragma unroll 1
    for (int i = 0; i < NCHUNK; i++) {
        CP_WAIT2();              // chunk i resident (2 newer groups outstanding)
        __syncthreads();
        const uint32_t base = smb + (uint32_t)(i & 3) * BUF_B;
#pragma unroll
        for (int q = 0; q < 2; q++) {
            const uint32_t qo = q * 32;
            uint32_t ah[4][4], bf[8][2];
#pragma unroll
            for (int f = 0; f < 4; f++)
                ldsm4(ah[f], base + aAddr + f * 1280 + qo);
#pragma unroll
            for (int t = 0; t < 4; t++) {
                uint32_t r[4];
                ldsm4(r, base + bAddr + t * 1280 + qo);
                bf[2 * t][0] = r[0]; bf[2 * t][1] = r[1];
                bf[2 * t + 1][0] = r[2]; bf[2 * t + 1][1] = r[3];
            }
#pragma unroll
            for (int f = 0; f < 4; f++)
#pragma unroll
                for (int j = 0; j < 8; j++)
                    mma_f16(acc[f][j], ah[f], bf[j]);
        }
        if (i + STAGES - 1 < NCHUNK)
            issue_chunk(i + STAGES - 1, smb + (uint32_t)((i + STAGES - 1) & 3) * BUF_B);
        CP_COMMIT();             // always commit: keeps group count uniform
    }

    // ---- epilogue: bias + relu, fp16 stores (all m < 512), guarded tail ----
    float bias_v[4][2];
#pragma unroll
    for (int f = 0; f < 4; f++)
#pragma unroll
        for (int h = 0; h < 2; h++)
            bias_v[f][h] = g_bias[mBase + mw * 64 + f * 16 + (lane >> 2) + 8 * h];
#pragma unroll
    for (int j = 0; j < 8; j++) {
        const int nj  = nBase + nw * 64 + j * 8 + (lane & 3) * 2;
        if (nj >= NDIM) continue;
        const int bj  = nj / P_;
        const int rj  = nj - bj * P_;
        const size_t fb = (size_t)bj * FEAT_BSTR + rj;
#pragma unroll
        for (int f = 0; f < 4; f++)
#pragma unroll
            for (int h = 0; h < 2; h++) {
                const int m = mBase + mw * 64 + f * 16 + (lane >> 2) + 8 * h;
                __half2 o = __floats2half2_rn(
                    fmaxf(acc[f][j][2 * h]     + bias_v[f][h], 0.f),
                    fmaxf(acc[f][j][2 * h + 1] + bias_v[f][h], 0.f));
                *(__half2*)(g_feats + fb + (size_t)m * P_) = o;
            }
    }
}

// ---------------- K1b: scores GEMM, k-split x4 with atomic merge ----------------
__global__ void __launch_bounds__(128) score_mma() {
    extern __shared__ char sm[];
    const uint32_t smb = smem_u32(sm);
    const int tid  = threadIdx.x;
    const int wid  = tid >> 5;      // 0..3 = n-warp
    const int lane = tid & 31;
    const int nBase = blockIdx.x * SNT;
    const int cBase = blockIdx.y * SCHUNK;     // chunk segment

    // B loader: row = tid, 4 chunks
    const int n   = nBase + tid;
    const int b2  = n / P_;
    const int rem = n - b2 * P_;
    const int ho  = rem / W_;
    const int w   = rem - ho * W_;
    const size_t bRowBase = ((size_t)(b2 * 16 + ho) * W_ + w) * C_;
    // A loader: 64 transfers: 16 rows * 4 chunks (tid < 64)
    const int arow = (tid & 63) >> 2;
    const int ac16 = tid & 3;
    const bool aact = tid < 64;
    const __half* aPtr = g_wh + (size_t)(512 + arow) * KDIM + ac16 * 8;
    const uint32_t aSoff = (uint32_t)(arow * ROWB + ac16 * 16);

    const uint32_t aAddr = (uint32_t)((lane & 15) * ROWB + ((lane >> 4) << 4));
    const uint32_t bAddr = (uint32_t)(S_ATILE +
                           (wid * 32 + (lane & 7) + ((lane >> 4) << 3)) * ROWB +
                           (((lane >> 3) & 1) << 4));

    float acc[4][4];
#pragma unroll
    for (int j = 0; j < 4; j++)
#pragma unroll
        for (int r = 0; r < 4; r++) acc[j][r] = 0.f;

    // prologue: chunk cBase
    {
        const int k0  = cBase << 5;
        const int kh  = k0 >> 9;
        const int ci0 = k0 & 511;
        const size_t bo = (size_t)kh * (W_ * C_) + ci0;
        uint4 vb[4];
#pragma unroll
        for (int c = 0; c < 4; c++) vb[c] = *(const uint4*)(g_xh + bRowBase + bo + c * 8);
        if (aact) *(uint4*)(sm + aSoff) = *(const uint4*)(aPtr + k0);
#pragma unroll
        for (int c = 0; c < 4; c++)
            *(uint4*)(sm + S_ATILE + tid * ROWB + c * 16) = vb[c];
    }
    __syncthreads();

#pragma unroll 1
    for (int i = 0; i < SCHUNK; i++) {
        const int cur = i & 1;
        uint4 va, vb[4];
        const bool hasNext = (i + 1) < SCHUNK;
        if (hasNext) {
            const int k0  = (cBase + i + 1) << 5;
            const int kh  = k0 >> 9;
            const int ci0 = k0 & 511;
            const size_t bo = (size_t)kh * (W_ * C_) + ci0;
            if (aact) va = *(const uint4*)(aPtr + k0);
#pragma unroll
            for (int c = 0; c < 4; c++) vb[c] = *(const uint4*)(g_xh + bRowBase + bo + c * 8);
        }
        {
            const uint32_t base = smb + (uint32_t)cur * S_BUF;
#pragma unroll
            for (int q = 0; q < 2; q++) {
                const uint32_t qo = q * 32;
                uint32_t ah[4], bf[4][2];
                ldsm4(ah, base + aAddr + qo);
#pragma unroll
                for (int t = 0; t < 2; t++) {
                    uint32_t r[4];
                    ldsm4(r, base + bAddr + t * 1280 + qo);
                    bf[2 * t][0] = r[0]; bf[2 * t][1] = r[1];
                    bf[2 * t + 1][0] = r[2]; bf[2 * t + 1][1] = r[3];
                }
#pragma unroll
                for (int j = 0; j < 4; j++)
                    mma_f16(acc[j], ah, bf[j]);
            }
        }
        if (hasNext) {
            char* bb = sm + (cur ^ 1) * S_BUF;
            if (aact) *(uint4*)(bb + aSoff) = va;
#pragma unroll
            for (int c = 0; c < 4; c++)
                *(uint4*)(bb + S_ATILE + tid * ROWB + c * 16) = vb[c];
        }
        __syncthreads();
    }

    // epilogue: rows 0..9 real -> atomic merge into scores
#pragma unroll
    for (int j = 0; j < 4; j++) {
        const int nj  = nBase + wid * 32 + j * 8 + (lane & 3) * 2;
        const int bj  = nj / P_;
        const int rj  = nj - bj * P_;
        const size_t sb = (size_t)bj * SCOR_BSTR + rj;
#pragma unroll
        for (int h = 0; h < 2; h++) {
            const int m = (lane >> 2) + 8 * h;
            if (m < KG_) {
                atomicAdd(g_scores + sb + (size_t)m * P_,     acc[j][2 * h]);
                atomicAdd(g_scores + sb + (size_t)m * P_ + 1, acc[j][2 * h + 1]);
            }
        }
    }
}

// ---------------- K2: softmax over 10 cluster channels ----------------
__global__ void softmax_kernel() {
    int q = blockIdx.x * 256 + threadIdx.x;
    if (q >= NDIM) return;
    int b = q / P_;
    int rem = q - b * P_;
    int base = b * SCOR_BSTR + rem;
    float s[KG_];
    float mx = -1e30f;
#pragma unroll
    for (int k = 0; k < KG_; k++) { s[k] = g_scores[base + k * P_]; mx = fmaxf(mx, s[k]); }
    float sum = 0.f;
#pragma unroll
    for (int k = 0; k < KG_; k++) { s[k] = expf(s[k] - mx); sum += s[k]; }
    float inv = 1.f / sum;
#pragma unroll
    for (int k = 0; k < KG_; k++) g_assign[base + k * P_] = s[k] * inv;
}

// ---------------- K2b: asum ----------------
__global__ void asum_kernel() {
    int b = blockIdx.x >> 3, k = blockIdx.x & 7;
    const float* a = g_assign + b * SCOR_BSTR + k * P_;
    float s = 0.f;
    for (int i = threadIdx.x; i < P_; i += 256) s += a[i];
    __shared__ float red[256];
    red[threadIdx.x] = s;
    __syncthreads();
    for (int st = 128; st > 0; st >>= 1) {
        if (threadIdx.x < st) red[threadIdx.x] += red[threadIdx.x + st];
        __syncthreads();
    }
    if (threadIdx.x == 0) g_asum[blockIdx.x] = red[0];
}

// ---------------- K3: agg, p-split x4, atomic merge ----------------
__global__ void agg_kernel() {
    __shared__ float fs[64][65];
    __shared__ float as[8][64];
    const int b  = blockIdx.y;
    const int c0 = blockIdx.x * 64;
    const int pg = blockIdx.z;           // p segment
    const int t = threadIdx.x;
    const int k = t >> 6;
    const int c = t & 63;
    const __half* fb = g_feats + (size_t)b * FEAT_BSTR + (size_t)c0 * P_;
    const float* ab = g_assign + b * SCOR_BSTR;
    float acc0 = 0.f, acc1 = 0.f;
    const int pStart = pg * PSEG;
    const int pEnd   = pStart + PSEG;
    for (int p0 = pStart; p0 < pEnd; p0 += 64) {
        int pc = pEnd - p0; if (pc > 64) pc = 64;
#pragma unroll
        for (int idx = t; idx < 4096; idx += 256) {
            int cc = idx >> 6, pp = idx & 63;
            fs[cc][pp] = (pp < pc) ? __half2float(fb[cc * P_ + p0 + pp]) : 0.f;
        }
#pragma unroll
        for (int idx = t; idx < 512; idx += 256) {
            int kk = idx >> 6, pp = idx & 63;
            as[kk][pp] = (pp < pc) ? ab[kk * P_ + p0 + pp] : 0.f;
        }
        __syncthreads();
#pragma unroll
        for (int p = 0; p < 64; p++) {
            float f = fs[c][p];
            acc0 = fmaf(as[k][p], f, acc0);
            acc1 = fmaf(as[k + 4][p], f, acc1);
        }
        __syncthreads();
    }
    atomicAdd(g_agg + b * 4096 + k * 512 + c0 + c,       acc0);
    atomicAdd(g_agg + b * 4096 + (k + 4) * 512 + c0 + c, acc1);
}

// ---------------- K4: residual + L2 normalize ----------------
__global__ void vlad_kernel(const float* __restrict__ centroids) {
    const int b = blockIdx.x >> 3, k = blockIdx.x & 7;
    const int t = threadIdx.x;
    const float asum = g_asum[blockIdx.x];
    const float* aggp = g_agg + b * 4096 + k * 512;
    const float* cen = centroids + k * 512;
    float r0 = aggp[t] - asum * cen[t];
    float r1 = aggp[t + 256] - asum * cen[t + 256];
    __shared__ float red[256];
    red[t] = r0 * r0 + r1 * r1;
    __syncthreads();
    for (int st = 128; st > 0; st >>= 1) {
        if (t < st) red[t] += red[t + st];
        __syncthreads();
    }
    __shared__ float scale_s;
    if (t == 0) scale_s = 1.f / fmaxf(sqrtf(red[0]), 1e-12f);
    __syncthreads();
    float sc = scale_s;
    g_vlad[b * 4096 + k * 512 + t] = r0 * sc;
    g_vlad[b * 4096 + k * 512 + t + 256] = r1 * sc;
}

// ---------------- K5: emb, one CTA per channel, fc_w row staged in smem ------
__global__ void __launch_bounds__(128) emb_kernel(const float* __restrict__ fc_w,
                                                  const float* __restrict__ fc_b,
                                                  float* __restrict__ out) {
    const int co = blockIdx.x;
    __shared__ __align__(16) float ws[4096];
    const int t = threadIdx.x;          // 128
    const int wid = t >> 5, lane = t & 31;
    {
        const float4* wr = (const float4*)(fc_w + (size_t)co * 4096);
        float4* wsv = (float4*)ws;
#pragma unroll
        for (int i = t; i < 1024; i += 128) wsv[i] = wr[i];
    }
    __syncthreads();
    const float bv = fc_b[co];
    const float4* wsv = (const float4*)ws;
#pragma unroll
    for (int bb = 0; bb < 4; bb++) {
        const int b = wid * 4 + bb;
        const float4* v = (const float4*)(g_vlad + b * 4096);
        float s = 0.f;
        for (int i = lane; i < 1024; i += 32) {
            float4 a = v[i], w4 = wsv[i];
            s += a.x * w4.x + a.y * w4.y + a.z * w4.z + a.w * w4.w;
        }
#pragma unroll
        for (int off = 16; off > 0; off >>= 1)
            s += __shfl_down_sync(0xffffffff, s, off);
        if (lane == 0) out[b * 512 + co] = fmaxf(s + bv, 0.f);
    }
}

// ---------------- K6: logit, one CTA per output row, w staged in smem ----------
__global__ void __launch_bounds__(128) logit_kernel(const float* __restrict__ emb,
                                                    const float* __restrict__ lw,
                                                    float* __restrict__ out) {
    const int o = blockIdx.x;
    __shared__ __align__(16) float ws[512];
    const int t = threadIdx.x;          // 128
    const int wid = t >> 5, lane = t & 31;
    {
        const float4* wr = (const float4*)(lw + (size_t)o * 512);
        float4* wsv = (float4*)ws;
#pragma unroll
        for (int i = t; i < 128; i += 128) wsv[i] = wr[i];
    }
    __syncthreads();
    const float4* wsv = (const float4*)ws;
#pragma unroll
    for (int bb = 0; bb < 4; bb++) {
        const int b = wid * 4 + bb;
        const float4* e = (const float4*)(emb + b * 512);
        float s = 0.f;
#pragma unroll
        for (int i = lane; i < 128; i += 32) {
            float4 a = e[i], w4 = wsv[i];
            s += a.x * w4.x + a.y * w4.y + a.z * w4.z + a.w * w4.w;
        }
#pragma unroll
        for (int off = 16; off > 0; off >>= 1)
            s += __shfl_down_sync(0xffffffff, s, off);
        if (lane == 0) out[b * OUT_ + o] = s;
    }
}

// ---------------- launch ----------------
extern "C" void kernel_launch(void* const* d_in, const int* in_sizes, int n_in,
                              void* d_out, int out_size) {
    const float* x5        = (const float*)d_in[0];
    const float* conv_w    = (const float*)d_in[5];
    const float* conv_b    = (const float*)d_in[6];
    const float* cc_w      = (const float*)d_in[7];
    const float* cc_b      = (const float*)d_in[8];
    const float* centroids = (const float*)d_in[9];
    const float* fc_w      = (const float*)d_in[10];
    const float* fc_b      = (const float*)d_in[11];
    const float* logit_w   = (const float*)d_in[12];
    float* out = (float*)d_out;

    // lazy one-time setup (first call happens OUTSIDE graph capture)
    static cudaStream_t s2 = nullptr;
    static cudaEvent_t evFork = nullptr, evJoin = nullptr;
    if (s2 == nullptr) {
        cudaStreamCreateWithFlags(&s2, cudaStreamNonBlocking);
        cudaEventCreateWithFlags(&evFork, cudaEventDisableTiming);
        cudaEventCreateWithFlags(&evJoin, cudaEventDisableTiming);
        cudaFuncSetAttribute(conv_mma, cudaFuncAttributeMaxDynamicSharedMemorySize, SMEM_TOTAL);
    }

    pack_kernel<<<(MPAD * KDIM + 255) / 256, 256>>>(conv_w, conv_b, cc_w, cc_b);
    init_scores<<<(B_ * SCOR_BSTR + 255) / 256, 256>>>();
    xt_kernel<<<dim3(160, 256), 256>>>(x5);

    // fork: score chain on s2, conv on main stream
    cudaEventRecord(evFork, 0);
    cudaStreamWaitEvent(s2, evFork, 0);
    score_mma<<<dim3(NDIM / SNT, KSPLIT), 128, S_SMEM, s2>>>();
    softmax_kernel<<<(NDIM + 255) / 256, 256, 0, s2>>>();
    asum_kernel<<<B_ * KC_, 256, 0, s2>>>();
    cudaEventRecord(evJoin, s2);

    conv_mma<<<dim3((NDIM + NT - 1) / NT, 4), 256, SMEM_TOTAL>>>();

    // join: agg needs feats (main) + assign (s2)
    cudaStreamWaitEvent(0, evJoin, 0);
    agg_kernel<<<dim3(8, B_, PSPLIT), 256>>>();
    vlad_kernel<<<B_ * KC_, 256>>>(centroids);
    emb_kernel<<<C_, 128>>>(fc_w, fc_b, out);
    logit_kernel<<<OUT_, 128>>>(out, logit_w, out + B_ * C_);
}